// round 12
// baseline (speedup 1.0000x reference)
#include <cuda_runtime.h>
#include <cstdint>

// Problem constants
#define N_ROWS 8192
#define D_COLS 1024
#define NBLK1  256                      // kernel1 blocks (1024 threads each)
// block covers 32 rows = 32768 floats = 4096 8-float groups, 4 iters x 1024
// Scratch: per-block folded column sums [256][1024] floats = 1 MB
__device__ float g_partial[NBLK1 * D_COLS];
// stage-2: [32][1024] floats = 128 KB
__device__ float g_partial2[32 * D_COLS];

struct f8 { float4 a, b; };

// src load: 256-bit, L2 evict_last (pin 32 MB src half in L2 across replays)
__device__ __forceinline__ f8 ldg256_keep(const float* p) {
    f8 v; uint32_t r0,r1,r2,r3,r4,r5,r6,r7;
    asm("ld.global.nc.L2::evict_last.v8.b32 {%0,%1,%2,%3,%4,%5,%6,%7}, [%8];"
        : "=r"(r0),"=r"(r1),"=r"(r2),"=r"(r3),
          "=r"(r4),"=r"(r5),"=r"(r6),"=r"(r7) : "l"(p));
    v.a.x=__uint_as_float(r0); v.a.y=__uint_as_float(r1);
    v.a.z=__uint_as_float(r2); v.a.w=__uint_as_float(r3);
    v.b.x=__uint_as_float(r4); v.b.y=__uint_as_float(r5);
    v.b.z=__uint_as_float(r6); v.b.w=__uint_as_float(r7);
    return v;
}

// tgt load: 256-bit, L2 evict_first (stream; don't displace pinned src)
__device__ __forceinline__ f8 ldg256_stream(const float* p) {
    f8 v; uint32_t r0,r1,r2,r3,r4,r5,r6,r7;
    asm("ld.global.nc.L2::evict_first.v8.b32 {%0,%1,%2,%3,%4,%5,%6,%7}, [%8];"
        : "=r"(r0),"=r"(r1),"=r"(r2),"=r"(r3),
          "=r"(r4),"=r"(r5),"=r"(r6),"=r"(r7) : "l"(p));
    v.a.x=__uint_as_float(r0); v.a.y=__uint_as_float(r1);
    v.a.z=__uint_as_float(r2); v.a.w=__uint_as_float(r3);
    v.b.x=__uint_as_float(r4); v.b.y=__uint_as_float(r5);
    v.b.z=__uint_as_float(r6); v.b.w=__uint_as_float(r7);
    return v;
}

// ---------------------------------------------------------------------------
// Kernel 1: streaming column-sum of (source - target), 256-bit loads.
// 256 blocks x 1024 threads; thread t handles 8-float group t + k*1024
// (k=0..3). 1024 groups = 8 rows, so thread t's columns ((t%128)*8..+7)
// are iteration-invariant. Exit: 8-way smem fold -> 1024 floats per block.
// ---------------------------------------------------------------------------
__global__ __launch_bounds__(1024)
void mmd_colsum_kernel(const float* __restrict__ src,
                       const float* __restrict__ tgt) {
    const int t   = threadIdx.x;               // 0..1023
    const int blk = blockIdx.x;                // 0..255
    const long base = (long)blk * 32768 + (long)t * 8;

    float4 accA = {0.f,0.f,0.f,0.f};
    float4 accB = {0.f,0.f,0.f,0.f};

#pragma unroll
    for (int k = 0; k < 4; k++) {
        const long off = base + (long)k * 8192;
        f8 s = ldg256_keep(src + off);
        f8 v = ldg256_stream(tgt + off);
        accA.x += s.a.x - v.a.x;  accA.y += s.a.y - v.a.y;
        accA.z += s.a.z - v.a.z;  accA.w += s.a.w - v.a.w;
        accB.x += s.b.x - v.b.x;  accB.y += s.b.y - v.b.y;
        accB.z += s.b.z - v.b.z;  accB.w += s.b.w - v.b.w;
    }

    // 8-way fold: threads with equal (t % 128) share the same 8 columns
    __shared__ float4 redA[1024];
    __shared__ float4 redB[1024];
    redA[t] = accA;
    redB[t] = accB;
    __syncthreads();
    if (t < 128) {
#pragma unroll
        for (int j = 1; j < 8; j++) {
            float4 rA = redA[t + j * 128];
            float4 rB = redB[t + j * 128];
            accA.x += rA.x; accA.y += rA.y; accA.z += rA.z; accA.w += rA.w;
            accB.x += rB.x; accB.y += rB.y; accB.z += rB.z; accB.w += rB.w;
        }
        float4* dst = reinterpret_cast<float4*>(&g_partial[blk * D_COLS + t * 8]);
        dst[0] = accA;                          // cached stores: stay in L2
        dst[1] = accB;
    }
}

// ---------------------------------------------------------------------------
// Kernel 2: reduce 256 partial rows -> 32 rows. 32 blocks x 1024 threads;
// block b sums partial rows [b*8, b*8+8) for its column. L2-hot. PDL-gated.
// ---------------------------------------------------------------------------
__global__ __launch_bounds__(1024)
void mmd_reduce_kernel() {
    cudaGridDependencySynchronize();           // wait for kernel1 completion
    const int d = threadIdx.x;                 // column 0..1023
    const int b = blockIdx.x;                  // 0..31

    float s = 0.f;
#pragma unroll
    for (int r = 0; r < 8; r++) {
        s += g_partial[(long)(b * 8 + r) * D_COLS + d];
    }
    g_partial2[b * D_COLS + d] = s;
}

// ---------------------------------------------------------------------------
// Kernel 3: finish column sums over 32 rows (128 KB, L2-hot), square,
// block-reduce 1024 lanes, scale, write scalar. Fixed order. PDL-gated.
// ---------------------------------------------------------------------------
__global__ __launch_bounds__(1024)
void mmd_final_kernel(float* __restrict__ out) {
    cudaGridDependencySynchronize();           // wait for kernel2 completion
    const int d = threadIdx.x;                 // column 0..1023

    float s = 0.f;
#pragma unroll
    for (int r = 0; r < 32; r++) {
        s += g_partial2[r * D_COLS + d];
    }
    float sq = s * s;

    __shared__ float red[1024];
    red[d] = sq;
    __syncthreads();
#pragma unroll
    for (int off = 512; off > 0; off >>= 1) {
        if (d < off) red[d] += red[d + off];
        __syncthreads();
    }
    if (d == 0)
        out[0] = red[0] * (1.0f / ((float)N_ROWS * (float)N_ROWS));
}

// ---------------------------------------------------------------------------
extern "C" void kernel_launch(void* const* d_in, const int* in_sizes, int n_in,
                              void* d_out, int out_size) {
    const float* src = (const float*)d_in[0];
    const float* tgt = (const float*)d_in[1];
    float* out = (float*)d_out;

    mmd_colsum_kernel<<<NBLK1, 1024>>>(src, tgt);

    // PDL launches: overlap launch/prologue with the predecessor kernel.
    cudaLaunchAttribute attr[1];
    attr[0].id = cudaLaunchAttributeProgrammaticStreamSerialization;
    attr[0].val.programmaticStreamSerializationAllowed = 1;

    {
        cudaLaunchConfig_t cfg = {};
        cfg.gridDim  = dim3(32, 1, 1);
        cfg.blockDim = dim3(1024, 1, 1);
        cfg.dynamicSmemBytes = 0;
        cfg.stream = 0;
        cfg.attrs = attr;
        cfg.numAttrs = 1;
        cudaLaunchKernelEx(&cfg, mmd_reduce_kernel);
    }
    {
        cudaLaunchConfig_t cfg = {};
        cfg.gridDim  = dim3(1, 1, 1);
        cfg.blockDim = dim3(1024, 1, 1);
        cfg.dynamicSmemBytes = 0;
        cfg.stream = 0;
        cfg.attrs = attr;
        cfg.numAttrs = 1;
        cudaLaunchKernelEx(&cfg, mmd_final_kernel, out);
    }
}

// round 13
// speedup vs baseline: 1.0245x; 1.0245x over previous
#include <cuda_runtime.h>
#include <cstdint>

// Problem constants
#define N_ROWS 8192
#define D_COLS 1024
#define D4     256                      // float4 columns per row
#define NBLK1  256                      // kernel1 blocks (1024 threads each)
#define ITERS  8                        // 8 quads = 32 rows per block
#define NBLK2  32                       // tail blocks

// Scratch: per-block folded column sums [256][1024] floats = 1 MB
__device__ float4 g_partial[NBLK1 * D4];
// stage-2: [32][1024] floats = 128 KB
__device__ float  g_partial2[NBLK2 * D_COLS];
// ticket for last-block-finishes (reset by the last block each launch)
__device__ unsigned int g_ticket = 0;

// Input load with 256B L2 fetch-granularity hint (dense stream, no waste)
__device__ __forceinline__ float4 ldg_256B(const float4* p) {
    float4 v;
    asm("ld.global.nc.L2::256B.v4.f32 {%0,%1,%2,%3}, [%4];"
        : "=f"(v.x), "=f"(v.y), "=f"(v.z), "=f"(v.w) : "l"(p));
    return v;
}

// ---------------------------------------------------------------------------
// Kernel 1 (frozen round-10 config): streaming column-sum of (src - tgt).
// 256 blocks x 1024 threads; static unrolled loop of 8 quad-rows (32 rows).
// Thread t's float4 column group (t%256) is fixed across iterations.
// Exit: 4-way smem fold -> 256 float4 per block (1 MB total scratch).
// ---------------------------------------------------------------------------
__global__ __launch_bounds__(1024)
void mmd_colsum_kernel(const float4* __restrict__ src,
                       const float4* __restrict__ tgt) {
    const int t   = threadIdx.x;               // 0..1023
    const int blk = blockIdx.x;                // 0..255
    const long base = (long)blk * (ITERS * 1024) + t;

    float ax = 0.f, ay = 0.f, az = 0.f, aw = 0.f;

#pragma unroll
    for (int i = 0; i < ITERS; i++) {
        const long off = base + (long)i * 1024;
        float4 s = ldg_256B(&src[off]);
        float4 v = ldg_256B(&tgt[off]);
        ax += s.x - v.x;
        ay += s.y - v.y;
        az += s.z - v.z;
        aw += s.w - v.w;
    }

    __shared__ float4 red[1024];
    float4 acc; acc.x = ax; acc.y = ay; acc.z = az; acc.w = aw;
    red[t] = acc;
    __syncthreads();
    if (t < 256) {
        float4 r1 = red[t + 256];
        float4 r2 = red[t + 512];
        float4 r3 = red[t + 768];
        acc = red[t];
        acc.x += r1.x + r2.x + r3.x;
        acc.y += r1.y + r2.y + r3.y;
        acc.z += r1.z + r2.z + r3.z;
        acc.w += r1.w + r2.w + r3.w;
        g_partial[blk * D4 + t] = acc;         // cached store: stays in L2
    }
}

// ---------------------------------------------------------------------------
// Kernel 2 (merged tail): 32 blocks x 1024 threads, PDL-gated on kernel1.
// Phase A: block b reduces partial rows [b*8, b*8+8) -> g_partial2 row b.
// Phase B: the LAST block to finish (int ticket; deterministic value since
// all rows are complete and the read order is fixed) reduces the 128 KB
// stage-2 buffer, squares, tree-reduces, scales, writes the scalar, and
// resets the ticket for the next graph replay.
// ---------------------------------------------------------------------------
__global__ __launch_bounds__(1024)
void mmd_tail_kernel(float* __restrict__ out) {
    cudaGridDependencySynchronize();           // wait for kernel1 completion
    const int d = threadIdx.x;                 // column 0..1023
    const int b = blockIdx.x;                  // 0..31
    const float* p = reinterpret_cast<const float*>(g_partial);

    float s = 0.f;
#pragma unroll
    for (int r = 0; r < 8; r++) {
        s += p[(long)(b * 8 + r) * D_COLS + d];
    }
    g_partial2[b * D_COLS + d] = s;

    // make this block's row visible, then take a ticket
    __threadfence();
    __shared__ unsigned int is_last;
    if (d == 0) {
        unsigned int prev = atomicAdd(&g_ticket, 1u);
        is_last = (prev == NBLK2 - 1) ? 1u : 0u;
    }
    __syncthreads();
    if (!is_last) return;
    __threadfence();                           // acquire all rows

    float tsum = 0.f;
#pragma unroll
    for (int r = 0; r < NBLK2; r++) {
        tsum += g_partial2[r * D_COLS + d];
    }
    float sq = tsum * tsum;

    __shared__ float red[1024];
    red[d] = sq;
    __syncthreads();
#pragma unroll
    for (int off = 512; off > 0; off >>= 1) {
        if (d < off) red[d] += red[d + off];
        __syncthreads();
    }
    if (d == 0) {
        out[0] = red[0] * (1.0f / ((float)N_ROWS * (float)N_ROWS));
        g_ticket = 0;                          // reset for next replay
    }
}

// ---------------------------------------------------------------------------
extern "C" void kernel_launch(void* const* d_in, const int* in_sizes, int n_in,
                              void* d_out, int out_size) {
    const float4* src = (const float4*)d_in[0];
    const float4* tgt = (const float4*)d_in[1];
    float* out = (float*)d_out;

    mmd_colsum_kernel<<<NBLK1, 1024>>>(src, tgt);

    // PDL launch: overlap tail launch/prologue with kernel1.
    cudaLaunchAttribute attr[1];
    attr[0].id = cudaLaunchAttributeProgrammaticStreamSerialization;
    attr[0].val.programmaticStreamSerializationAllowed = 1;

    cudaLaunchConfig_t cfg = {};
    cfg.gridDim  = dim3(NBLK2, 1, 1);
    cfg.blockDim = dim3(1024, 1, 1);
    cfg.dynamicSmemBytes = 0;
    cfg.stream = 0;
    cfg.attrs = attr;
    cfg.numAttrs = 1;
    cudaLaunchKernelEx(&cfg, mmd_tail_kernel, out);
}

// round 14
// speedup vs baseline: 1.1471x; 1.1197x over previous
#include <cuda_runtime.h>
#include <cstdint>

// Problem constants
#define N_ROWS 8192
#define D_COLS 1024
#define D4     256                      // float4 columns per row
#define NBLK1  256                      // kernel1 blocks (1024 threads each)
#define ITERS  8                        // 8 quads = 32 rows per block
#define NBLK2  32                       // stage-2 blocks

// Scratch: per-block folded column sums [256][1024] floats = 1 MB
__device__ float4 g_partial[NBLK1 * D4];
// stage-2: [32][1024] floats = 128 KB
__device__ float  g_partial2[NBLK2 * D_COLS];

// Input load with 256B L2 fetch-granularity hint (dense stream, no waste)
__device__ __forceinline__ float4 ldg_256B(const float4* p) {
    float4 v;
    asm("ld.global.nc.L2::256B.v4.f32 {%0,%1,%2,%3}, [%4];"
        : "=f"(v.x), "=f"(v.y), "=f"(v.z), "=f"(v.w) : "l"(p));
    return v;
}

// ---------------------------------------------------------------------------
// Kernel 1: streaming column-sum of (source - target).
// 256 blocks x 1024 threads; static unrolled loop of 8 quad-rows (32 rows).
// Thread t's float4 column group (t%256) is fixed across iterations.
// Exit: 4-way smem fold -> 256 float4 per block (1 MB total scratch).
// ---------------------------------------------------------------------------
__global__ __launch_bounds__(1024)
void mmd_colsum_kernel(const float4* __restrict__ src,
                       const float4* __restrict__ tgt) {
    const int t   = threadIdx.x;               // 0..1023
    const int blk = blockIdx.x;                // 0..255
    const long base = (long)blk * (ITERS * 1024) + t;

    float ax = 0.f, ay = 0.f, az = 0.f, aw = 0.f;

#pragma unroll
    for (int i = 0; i < ITERS; i++) {
        const long off = base + (long)i * 1024;
        float4 s = ldg_256B(&src[off]);
        float4 v = ldg_256B(&tgt[off]);
        ax += s.x - v.x;
        ay += s.y - v.y;
        az += s.z - v.z;
        aw += s.w - v.w;
    }

    __shared__ float4 red[1024];
    float4 acc; acc.x = ax; acc.y = ay; acc.z = az; acc.w = aw;
    red[t] = acc;
    __syncthreads();
    if (t < 256) {
        float4 r1 = red[t + 256];
        float4 r2 = red[t + 512];
        float4 r3 = red[t + 768];
        acc = red[t];
        acc.x += r1.x + r2.x + r3.x;
        acc.y += r1.y + r2.y + r3.y;
        acc.z += r1.z + r2.z + r3.z;
        acc.w += r1.w + r2.w + r3.w;
        g_partial[blk * D4 + t] = acc;         // cached store: stays in L2
    }
}

// ---------------------------------------------------------------------------
// Kernel 2: reduce 256 partial rows -> 32 rows. 32 blocks x 1024 threads;
// block b sums partial rows [b*8, b*8+8) for its column. L2-hot.
// PDL: launched with programmatic serialization; prologue overlaps kernel1.
// ---------------------------------------------------------------------------
__global__ __launch_bounds__(1024)
void mmd_reduce_kernel() {
    cudaGridDependencySynchronize();           // wait for kernel1 completion
    const int d = threadIdx.x;                 // column 0..1023
    const int b = blockIdx.x;                  // 0..31
    const float* p = reinterpret_cast<const float*>(g_partial);

    float s = 0.f;
#pragma unroll
    for (int r = 0; r < 8; r++) {
        s += p[(long)(b * 8 + r) * D_COLS + d];
    }
    g_partial2[b * D_COLS + d] = s;
}

// ---------------------------------------------------------------------------
// Kernel 3: finish column sums over 32 rows (128 KB, L2-hot), square,
// block-reduce 1024 lanes, scale, write scalar. Fixed order. PDL-gated.
// ---------------------------------------------------------------------------
__global__ __launch_bounds__(1024)
void mmd_final_kernel(float* __restrict__ out) {
    cudaGridDependencySynchronize();           // wait for kernel2 completion
    const int d = threadIdx.x;                 // column 0..1023

    float s = 0.f;
#pragma unroll
    for (int r = 0; r < 32; r++) {
        s += g_partial2[r * D_COLS + d];
    }
    float sq = s * s;

    __shared__ float red[1024];
    red[d] = sq;
    __syncthreads();
#pragma unroll
    for (int off = 512; off > 0; off >>= 1) {
        if (d < off) red[d] += red[d + off];
        __syncthreads();
    }
    if (d == 0)
        out[0] = red[0] * (1.0f / ((float)N_ROWS * (float)N_ROWS));
}

// ---------------------------------------------------------------------------
extern "C" void kernel_launch(void* const* d_in, const int* in_sizes, int n_in,
                              void* d_out, int out_size) {
    const float4* src = (const float4*)d_in[0];
    const float4* tgt = (const float4*)d_in[1];
    float* out = (float*)d_out;

    mmd_colsum_kernel<<<NBLK1, 1024>>>(src, tgt);

    // PDL launches: overlap launch/prologue with the predecessor kernel.
    cudaLaunchAttribute attr[1];
    attr[0].id = cudaLaunchAttributeProgrammaticStreamSerialization;
    attr[0].val.programmaticStreamSerializationAllowed = 1;

    {
        cudaLaunchConfig_t cfg = {};
        cfg.gridDim  = dim3(NBLK2, 1, 1);
        cfg.blockDim = dim3(1024, 1, 1);
        cfg.dynamicSmemBytes = 0;
        cfg.stream = 0;
        cfg.attrs = attr;
        cfg.numAttrs = 1;
        cudaLaunchKernelEx(&cfg, mmd_reduce_kernel);
    }
    {
        cudaLaunchConfig_t cfg = {};
        cfg.gridDim  = dim3(1, 1, 1);
        cfg.blockDim = dim3(1024, 1, 1);
        cfg.dynamicSmemBytes = 0;
        cfg.stream = 0;
        cfg.attrs = attr;
        cfg.numAttrs = 1;
        cudaLaunchKernelEx(&cfg, mmd_final_kernel, out);
    }
}